// round 13
// baseline (speedup 1.0000x reference)
#include <cuda_runtime.h>
#include <cuda_fp16.h>
#include <math.h>
#include <stdint.h>

#define NN 100000
#define NE 1600000
#define FIN 128
#define FH  128
#define NC  16
#define NB  98   // ceil(NN/1024)

typedef unsigned long long u64;

// packed fp32x2 helpers (Blackwell FFMA2 path — exact fp32, 2x fma-pipe rate)
#define FMA2(d, a, b) asm("fma.rn.f32x2 %0, %1, %2, %3;" : "=l"(d) : "l"(a), "l"(b), "l"(d))
#define ADD2(d, v)    asm("add.rn.f32x2 %0, %1, %2;"     : "=l"(d) : "l"(d), "l"(v))
#define DUP2(d, f)    asm("mov.b64 %0, {%1, %1};"        : "=l"(d) : "f"(f))
#define UNPK2(lo, hi, v) asm("mov.b64 {%0, %1}, %2;" : "=f"(lo), "=f"(hi) : "l"(v))

#define LDMX4(r0, r1, r2, r3, a) \
    asm volatile("ldmatrix.sync.aligned.m8n8.x4.shared.b16 {%0,%1,%2,%3}, [%4];" \
        : "=r"(r0), "=r"(r1), "=r"(r2), "=r"(r3) : "r"(a))
#define LDMX4T(r0, r1, r2, r3, a) \
    asm volatile("ldmatrix.sync.aligned.m8n8.x4.trans.shared.b16 {%0,%1,%2,%3}, [%4];" \
        : "=r"(r0), "=r"(r1), "=r"(r2), "=r"(r3) : "r"(a))
#define MMA16816(c, a, b0, b1) \
    asm volatile("mma.sync.aligned.m16n8k16.row.col.f32.f16.f16.f32 " \
        "{%0,%1,%2,%3}, {%4,%5,%6,%7}, {%8,%9}, {%0,%1,%2,%3};" \
        : "+f"((c)[0]), "+f"((c)[1]), "+f"((c)[2]), "+f"((c)[3]) \
        : "r"((a)[0]), "r"((a)[1]), "r"((a)[2]), "r"((a)[3]), "r"(b0), "r"(b1))

__device__ __forceinline__ uint32_t smem_u32(const void* p) {
    uint32_t a;
    asm("{ .reg .u64 t; cvta.to.shared.u64 t, %1; cvt.u32.u64 %0, t; }" : "=r"(a) : "l"(p));
    return a;
}

__device__ __forceinline__ int detect_is64(const void* e) {
    const int* p = (const int*)e;
    int allz = 1;
    #pragma unroll
    for (int k = 0; k < 16; k++)
        if (p[2 * k + 1] != 0) allz = 0;
    return allz;   // indices < 100000 -> if int64, every high word is 0
}

// ---------------- scratch (device globals; no allocation allowed) ----------
// g_count is SELF-CLEANING: zero at module load; k_scanC re-zeroes it after
// consuming, so every execution (incl. graph replays) sees zeros at entry.
__device__ int    g_count[NN];
__device__ int    g_rowptr[NN + 1];
__device__ int    g_rank[NE];              // per-edge rank within dst bucket
__device__ int    g_bsum[NB];
__device__ int    g_ssrc[NE];
__device__ float  g_dis[NN];
__device__ __half g_hs1h[(size_t)NN * FH];   // UNSCALED x@W1, fp16
__device__ __half g_a1h [(size_t)NN * FH];   // relu(agg1 + b1), fp16
__device__ __half g_hs2h[(size_t)NN * NC];   // dis-scaled a1@W2, fp16

// ------ histogram of dst + per-edge rank, 4 edges/thread, .cs edge reads ---
__global__ void k_hist(const void* __restrict__ e) {
    __shared__ int s64;
    if (threadIdx.x == 0) s64 = detect_is64(e);
    __syncthreads();
    int is64 = s64;
    int i = blockIdx.x * blockDim.x + threadIdx.x;
    if (i < NE / 4) {
        int d0, d1, d2, d3;
        if (is64) {
            longlong2 a = __ldcs(&((const longlong2*)e)[NE / 2 + 2 * i]);
            longlong2 b = __ldcs(&((const longlong2*)e)[NE / 2 + 2 * i + 1]);
            d0 = (int)a.x; d1 = (int)a.y; d2 = (int)b.x; d3 = (int)b.y;
        } else {
            int4 d = __ldcs(&((const int4*)e)[NE / 4 + i]);
            d0 = d.x; d1 = d.y; d2 = d.z; d3 = d.w;
        }
        int r0 = atomicAdd(&g_count[d0], 1);
        int r1 = atomicAdd(&g_count[d1], 1);
        int r2 = atomicAdd(&g_count[d2], 1);
        int r3 = atomicAdd(&g_count[d3], 1);
        ((int4*)g_rank)[i] = make_int4(r0, r1, r2, r3);
    }
}

// ---------------- scanA: per-1024-block exclusive scan ----------------------
__global__ void k_scanA() {
    __shared__ int sw[32];
    int tid = threadIdx.x, lane = tid & 31, w = tid >> 5;
    int idx = blockIdx.x * 1024 + tid;
    int v = (idx < NN) ? g_count[idx] : 0;
    int x = v;
    #pragma unroll
    for (int d = 1; d < 32; d <<= 1) {
        int t = __shfl_up_sync(0xffffffffu, x, d);
        if (lane >= d) x += t;
    }
    if (lane == 31) sw[w] = x;
    __syncthreads();
    if (w == 0) {
        int y = sw[lane];
        #pragma unroll
        for (int d = 1; d < 32; d <<= 1) {
            int t = __shfl_up_sync(0xffffffffu, y, d);
            if (lane >= d) y += t;
        }
        sw[lane] = y;
    }
    __syncthreads();
    int wpre = (w > 0) ? sw[w - 1] : 0;
    if (idx < NN) g_rowptr[idx] = wpre + x - v;
    if (tid == 1023) g_bsum[blockIdx.x] = wpre + x;
}

// ------ scanC: redundant scan of g_bsum + finalize rowptr/dis + CLEAN count -
__global__ void k_scanC() {
    __shared__ int boffS[NB];
    __shared__ int sw[4];
    int tid = threadIdx.x, lane = tid & 31, w = tid >> 5;
    int v = 0, x = 0;
    if (tid < 128) {
        v = (tid < NB) ? g_bsum[tid] : 0;
        x = v;
        #pragma unroll
        for (int d = 1; d < 32; d <<= 1) {
            int t = __shfl_up_sync(0xffffffffu, x, d);
            if (lane >= d) x += t;
        }
        if (lane == 31) sw[w] = x;
    }
    __syncthreads();
    if (tid < NB) {
        int woff = 0;
        for (int i = 0; i < w; i++) woff += sw[i];
        boffS[tid] = woff + x - v;
    }
    __syncthreads();
    int i = blockIdx.x * blockDim.x + tid;
    if (i < NN) {
        int cnt = g_count[i];
        g_count[i] = 0;                        // self-clean for next run
        int rp = g_rowptr[i] + boffS[i >> 10];
        g_rowptr[i] = rp;
        g_dis[i]    = rsqrtf((float)(cnt + 1));  // +1 self loop
        if (i == 0) g_rowptr[NN] = NE;
    }
}

// ------ counting-sort scatter — atomic-free, 4 edges/thread, .cs reads -----
__global__ void k_scatter(const void* __restrict__ e) {
    __shared__ int s64;
    if (threadIdx.x == 0) s64 = detect_is64(e);
    __syncthreads();
    int is64 = s64;
    int i = blockIdx.x * blockDim.x + threadIdx.x;
    if (i < NE / 4) {
        int s0, s1, s2, s3, d0, d1, d2, d3;
        if (is64) {
            longlong2 sa = __ldcs(&((const longlong2*)e)[2 * i]);
            longlong2 sb = __ldcs(&((const longlong2*)e)[2 * i + 1]);
            longlong2 da = __ldcs(&((const longlong2*)e)[NE / 2 + 2 * i]);
            longlong2 db = __ldcs(&((const longlong2*)e)[NE / 2 + 2 * i + 1]);
            s0 = (int)sa.x; s1 = (int)sa.y; s2 = (int)sb.x; s3 = (int)sb.y;
            d0 = (int)da.x; d1 = (int)da.y; d2 = (int)db.x; d3 = (int)db.y;
        } else {
            int4 s = __ldcs(&((const int4*)e)[i]);
            int4 d = __ldcs(&((const int4*)e)[NE / 4 + i]);
            s0 = s.x; s1 = s.y; s2 = s.z; s3 = s.w;
            d0 = d.x; d1 = d.y; d2 = d.z; d3 = d.w;
        }
        int4 rk = __ldcs(&((const int4*)g_rank)[i]);
        g_ssrc[g_rowptr[d0] + rk.x] = s0;
        g_ssrc[g_rowptr[d1] + rk.y] = s1;
        g_ssrc[g_rowptr[d2] + rk.z] = s2;
        g_ssrc[g_rowptr[d3] + rk.w] = s3;
    }
}

// ------ GEMM1 (mma.sync fp16): hs1h = fp16(x @ W1), 128x128x128 per CTA ----
// x/W reads use .cs (single-use) so hs1h output stays L2-resident for agg1.
#define SP 136   // smem pitch in halves
__global__ void __launch_bounds__(256, 2) k_gemm1(const float* __restrict__ x,
                                                  const float* __restrict__ W) {
    extern __shared__ char smem[];
    __half* As = (__half*)smem;            // [128][SP] x tile
    __half* Ws = (__half*)(smem + 128 * SP * 2);  // [128][SP] W1 (k-major)
    uint32_t sbA = smem_u32(As), sbW = smem_u32(Ws);
    int tid = threadIdx.x, wid = tid >> 5, lane = tid & 31;
    int wr = wid & 3, wc = wid >> 2;
    int blockRow = blockIdx.x * 128;

    #pragma unroll
    for (int it = 0; it < 16; it++) {
        int t = tid + it * 256;
        int r = t >> 5, c4 = (t & 31) * 4;
        int grow = blockRow + r;
        float4 v = make_float4(0.f, 0.f, 0.f, 0.f);
        if (grow < NN) v = __ldcs((const float4*)&x[(size_t)grow * FIN + c4]);
        __half2 h0 = __floats2half2_rn(v.x, v.y);
        __half2 h1 = __floats2half2_rn(v.z, v.w);
        *(uint2*)&As[r * SP + c4] = make_uint2(*(uint32_t*)&h0, *(uint32_t*)&h1);
    }
    #pragma unroll
    for (int it = 0; it < 16; it++) {
        int t = tid + it * 256;
        int k = t >> 5, n4 = (t & 31) * 4;
        float4 v = *(const float4*)&W[(size_t)k * FH + n4];
        __half2 h0 = __floats2half2_rn(v.x, v.y);
        __half2 h1 = __floats2half2_rn(v.z, v.w);
        *(uint2*)&Ws[k * SP + n4] = make_uint2(*(uint32_t*)&h0, *(uint32_t*)&h1);
    }
    __syncthreads();

    float c[2][8][4];
    #pragma unroll
    for (int mt = 0; mt < 2; mt++)
        #pragma unroll
        for (int nt = 0; nt < 8; nt++)
            #pragma unroll
            for (int i = 0; i < 4; i++) c[mt][nt][i] = 0.f;

    int lr = lane & 15, lh = lane >> 4;
    #pragma unroll
    for (int ks = 0; ks < 8; ks++) {
        uint32_t a[2][4];
        #pragma unroll
        for (int mt = 0; mt < 2; mt++) {
            uint32_t ad = sbA + ((wr * 32 + mt * 16 + lr) * SP + ks * 16 + 8 * lh) * 2;
            LDMX4(a[mt][0], a[mt][1], a[mt][2], a[mt][3], ad);
        }
        uint32_t b[4][4];
        #pragma unroll
        for (int np = 0; np < 4; np++) {
            uint32_t bd = sbW + ((ks * 16 + lr) * SP + wc * 64 + np * 16 + 8 * lh) * 2;
            LDMX4T(b[np][0], b[np][1], b[np][2], b[np][3], bd);
        }
        #pragma unroll
        for (int mt = 0; mt < 2; mt++)
            #pragma unroll
            for (int nt = 0; nt < 8; nt++)
                MMA16816(c[mt][nt], a[mt], b[nt >> 1][(nt & 1) * 2], b[nt >> 1][(nt & 1) * 2 + 1]);
    }
    __syncthreads();
    __half* stage = As;
    int g = lane >> 2, tc = (lane & 3) * 2;
    #pragma unroll
    for (int mt = 0; mt < 2; mt++)
        #pragma unroll
        for (int nt = 0; nt < 8; nt++) {
            int row = wr * 32 + mt * 16 + g;
            int col = wc * 64 + nt * 8 + tc;
            __half2 lo = __floats2half2_rn(c[mt][nt][0], c[mt][nt][1]);
            __half2 hi = __floats2half2_rn(c[mt][nt][2], c[mt][nt][3]);
            *(__half2*)&stage[row * SP + col] = lo;
            *(__half2*)&stage[(row + 8) * SP + col] = hi;
        }
    __syncthreads();
    #pragma unroll
    for (int it = 0; it < 8; it++) {
        int t = tid + it * 256;
        int r = t >> 4, c8 = (t & 15) * 8;
        int grow = blockRow + r;
        if (grow < NN)
            *(uint4*)&g_hs1h[(size_t)grow * FH + c8] = *(const uint4*)&stage[r * SP + c8];
    }
}

// ------ Agg layer 1: warp per node, half-warp per edge (R8 version) --------
__global__ void k_agg1(const float* __restrict__ b1) {
    int warp = threadIdx.x >> 5, lane = threadIdx.x & 31;
    int node = blockIdx.x * 8 + warp;
    if (node >= NN) return;   // warp-uniform
    int h = lane >> 4, q = lane & 15;
    const uint4* hv = (const uint4*)g_hs1h;
    float dnode = g_dis[node];
    u64 a0 = 0ULL, a1 = 0ULL, a2 = 0ULL, a3 = 0ULL;
    {   // self-loop only on half 0
        float ds = (h == 0) ? dnode : 0.f;
        u64 dd;
        DUP2(dd, ds);
        uint4 r = hv[(size_t)node * 16 + q];
        float2 f0 = __half22float2(*(__half2*)&r.x);
        float2 f1 = __half22float2(*(__half2*)&r.y);
        float2 f2 = __half22float2(*(__half2*)&r.z);
        float2 f3 = __half22float2(*(__half2*)&r.w);
        FMA2(a0, *(u64*)&f0, dd); FMA2(a1, *(u64*)&f1, dd);
        FMA2(a2, *(u64*)&f2, dd); FMA2(a3, *(u64*)&f3, dd);
    }
    int s0 = g_rowptr[node], s1 = g_rowptr[node + 1];
    for (int j = s0 + h; j < s1; j += 2) {
        int ss = __ldcs(&g_ssrc[j]);          // 16-lane broadcast
        float d = g_dis[ss];
        u64 dd;
        DUP2(dd, d);
        uint4 r = hv[(size_t)ss * 16 + q];
        float2 f0 = __half22float2(*(__half2*)&r.x);
        float2 f1 = __half22float2(*(__half2*)&r.y);
        float2 f2 = __half22float2(*(__half2*)&r.z);
        float2 f3 = __half22float2(*(__half2*)&r.w);
        FMA2(a0, *(u64*)&f0, dd); FMA2(a1, *(u64*)&f1, dd);
        FMA2(a2, *(u64*)&f2, dd); FMA2(a3, *(u64*)&f3, dd);
    }
    u64 o0 = __shfl_xor_sync(0xffffffffu, a0, 16);
    u64 o1 = __shfl_xor_sync(0xffffffffu, a1, 16);
    u64 o2 = __shfl_xor_sync(0xffffffffu, a2, 16);
    u64 o3 = __shfl_xor_sync(0xffffffffu, a3, 16);
    ADD2(a0, o0); ADD2(a1, o1); ADD2(a2, o2); ADD2(a3, o3);
    if (h == 0) {
        float f[8];
        UNPK2(f[0], f[1], a0); UNPK2(f[2], f[3], a1);
        UNPK2(f[4], f[5], a2); UNPK2(f[6], f[7], a3);
        float4 bA = ((const float4*)b1)[q * 2];
        float4 bB = ((const float4*)b1)[q * 2 + 1];
        float o[8];
        o[0] = fmaxf(fmaf(f[0], dnode, bA.x), 0.f);
        o[1] = fmaxf(fmaf(f[1], dnode, bA.y), 0.f);
        o[2] = fmaxf(fmaf(f[2], dnode, bA.z), 0.f);
        o[3] = fmaxf(fmaf(f[3], dnode, bA.w), 0.f);
        o[4] = fmaxf(fmaf(f[4], dnode, bB.x), 0.f);
        o[5] = fmaxf(fmaf(f[5], dnode, bB.y), 0.f);
        o[6] = fmaxf(fmaf(f[6], dnode, bB.z), 0.f);
        o[7] = fmaxf(fmaf(f[7], dnode, bB.w), 0.f);
        __half2 h0 = __floats2half2_rn(o[0], o[1]);
        __half2 h1 = __floats2half2_rn(o[2], o[3]);
        __half2 h2 = __floats2half2_rn(o[4], o[5]);
        __half2 h3 = __floats2half2_rn(o[6], o[7]);
        uint4 st = make_uint4(*(uint32_t*)&h0, *(uint32_t*)&h1,
                              *(uint32_t*)&h2, *(uint32_t*)&h3);
        ((uint4*)g_a1h)[(size_t)node * 16 + q] = st;
    }
}

// ------- GEMM2 (f32x2): hs2h[r] = fp16(dis[r] * (a1[r] @ W2)) ---------------
__global__ void k_gemm2(const float* __restrict__ W2) {
    __shared__ float as[64][132];
    __shared__ float ws2[FH * NC];
    int tid = threadIdx.x;
    int n  = tid >> 2;
    int cg = (tid & 3) * 4;
    int blockRow = blockIdx.x * 64;

    #pragma unroll
    for (int it = 0; it < 4; it++) {
        int t = tid + it * 256;
        int row = t >> 4, c8 = (t & 15) * 8;
        int grow = blockRow + row;
        uint4 r = make_uint4(0u, 0u, 0u, 0u);
        if (grow < NN) r = ((const uint4*)g_a1h)[(size_t)grow * 16 + (t & 15)];
        float2 f0 = __half22float2(*(__half2*)&r.x);
        float2 f1 = __half22float2(*(__half2*)&r.y);
        float2 f2 = __half22float2(*(__half2*)&r.z);
        float2 f3 = __half22float2(*(__half2*)&r.w);
        as[row][c8 + 0] = f0.x; as[row][c8 + 1] = f0.y;
        as[row][c8 + 2] = f1.x; as[row][c8 + 3] = f1.y;
        as[row][c8 + 4] = f2.x; as[row][c8 + 5] = f2.y;
        as[row][c8 + 6] = f3.x; as[row][c8 + 7] = f3.y;
    }
    #pragma unroll
    for (int i = 0; i < 8; i++) {
        int t = tid + i * 256;
        ws2[t] = W2[t];
    }
    __syncthreads();

    u64 acc2[2] = {0ULL, 0ULL};
    #pragma unroll 8
    for (int k = 0; k < FH; k++) {
        float av = as[n][k];
        u64 a2;
        DUP2(a2, av);
        ulonglong2 wv = *(const ulonglong2*)&ws2[k * NC + cg];
        FMA2(acc2[0], a2, wv.x);
        FMA2(acc2[1], a2, wv.y);
    }
    int row = blockRow + n;
    if (row < NN) {
        float l0, h0, l1, h1;
        UNPK2(l0, h0, acc2[0]); UNPK2(l1, h1, acc2[1]);
        float dv = g_dis[row];
        __half2 p0 = __floats2half2_rn(l0 * dv, h0 * dv);
        __half2 p1 = __floats2half2_rn(l1 * dv, h1 * dv);
        *(uint2*)&g_hs2h[(size_t)row * NC + cg] = make_uint2(*(uint32_t*)&p0, *(uint32_t*)&p1);
    }
}

// ------- Agg layer 2 + bias + log_softmax (2 lanes/node — R8 version) ------
__global__ void k_agg2(const float* __restrict__ b2, float* __restrict__ out) {
    int gt = blockIdx.x * blockDim.x + threadIdx.x;
    int node = gt >> 1;
    int q = gt & 1;
    int node_c = (node < NN) ? node : (NN - 1);
    const uint4* hv = (const uint4*)g_hs2h;   // 2 uint4 per row
    u64 aA0, aA1, aA2, aA3;
    {
        uint4 r = hv[(size_t)node_c * 2 + q];
        float2 f0 = __half22float2(*(__half2*)&r.x);
        float2 f1 = __half22float2(*(__half2*)&r.y);
        float2 f2 = __half22float2(*(__half2*)&r.z);
        float2 f3 = __half22float2(*(__half2*)&r.w);
        aA0 = *(u64*)&f0; aA1 = *(u64*)&f1; aA2 = *(u64*)&f2; aA3 = *(u64*)&f3;
    }
    int s0 = g_rowptr[node_c], s1 = g_rowptr[node_c + 1];
    for (int j = s0; j < s1; j++) {
        int s = __ldcs(&g_ssrc[j]);
        uint4 r = hv[(size_t)s * 2 + q];
        float2 f0 = __half22float2(*(__half2*)&r.x);
        float2 f1 = __half22float2(*(__half2*)&r.y);
        float2 f2 = __half22float2(*(__half2*)&r.z);
        float2 f3 = __half22float2(*(__half2*)&r.w);
        ADD2(aA0, *(u64*)&f0); ADD2(aA1, *(u64*)&f1);
        ADD2(aA2, *(u64*)&f2); ADD2(aA3, *(u64*)&f3);
    }
    float f[8];
    UNPK2(f[0], f[1], aA0); UNPK2(f[2], f[3], aA1);
    UNPK2(f[4], f[5], aA2); UNPK2(f[6], f[7], aA3);
    float dv = g_dis[node_c];
    float4 bA = ((const float4*)b2)[q * 2];
    float4 bB = ((const float4*)b2)[q * 2 + 1];
    float v[8];
    v[0] = fmaf(f[0], dv, bA.x); v[1] = fmaf(f[1], dv, bA.y);
    v[2] = fmaf(f[2], dv, bA.z); v[3] = fmaf(f[3], dv, bA.w);
    v[4] = fmaf(f[4], dv, bB.x); v[5] = fmaf(f[5], dv, bB.y);
    v[6] = fmaf(f[6], dv, bB.z); v[7] = fmaf(f[7], dv, bB.w);
    float m = v[0];
    #pragma unroll
    for (int i = 1; i < 8; i++) m = fmaxf(m, v[i]);
    m = fmaxf(m, __shfl_xor_sync(0xffffffffu, m, 1));
    float e = 0.f;
    #pragma unroll
    for (int i = 0; i < 8; i++) e += expf(v[i] - m);
    e += __shfl_xor_sync(0xffffffffu, e, 1);
    float lse = m + logf(e);
    if (node < NN) {
        float4 o0 = make_float4(v[0] - lse, v[1] - lse, v[2] - lse, v[3] - lse);
        float4 o1 = make_float4(v[4] - lse, v[5] - lse, v[6] - lse, v[7] - lse);
        ((float4*)out)[(size_t)node * 4 + q * 2]     = o0;
        ((float4*)out)[(size_t)node * 4 + q * 2 + 1] = o1;
    }
}

// -------- launch: serial single stream, 8 nodes, gemm1 adjacent to agg1 ----
extern "C" void kernel_launch(void* const* d_in, const int* in_sizes, int n_in,
                              void* d_out, int out_size) {
    const float* x  = (const float*)d_in[0];
    const void*  ei = d_in[1];
    const float* W1 = (const float*)d_in[2];
    const float* b1 = (const float*)d_in[3];
    const float* W2 = (const float*)d_in[4];
    const float* b2 = (const float*)d_in[5];
    float* out = (float*)d_out;

    const int GEMM1_SMEM = 2 * 128 * SP * 2;   // 69632
    cudaFuncSetAttribute(k_gemm1, cudaFuncAttributeMaxDynamicSharedMemorySize, GEMM1_SMEM);

    k_hist<<<(NE / 4 + 255) / 256, 256>>>(ei);          // 1
    k_scanA<<<NB, 1024>>>();                            // 2
    k_scanC<<<(NN + 255) / 256, 256>>>();               // 3
    k_scatter<<<(NE / 4 + 255) / 256, 256>>>(ei);       // 4 -> profiled
    k_gemm1<<<(NN + 127) / 128, 256, GEMM1_SMEM>>>(x, W1);  // 5 (right before agg1)
    k_agg1<<<(NN + 7) / 8, 256>>>(b1);                  // 6
    k_gemm2<<<(NN + 63) / 64, 256>>>(W2);               // 7
    k_agg2<<<(NN * 2 + 255) / 256, 256>>>(b2, out);     // 8
}

// round 14
// speedup vs baseline: 1.0425x; 1.0425x over previous
#include <cuda_runtime.h>
#include <cuda_fp16.h>
#include <math.h>
#include <stdint.h>

#define NN 100000
#define NE 1600000
#define FIN 128
#define FH  128
#define NC  16
#define NB  98   // ceil(NN/1024)

typedef unsigned long long u64;

// packed fp32x2 helpers (Blackwell FFMA2 path — exact fp32, 2x fma-pipe rate)
#define FMA2(d, a, b) asm("fma.rn.f32x2 %0, %1, %2, %3;" : "=l"(d) : "l"(a), "l"(b), "l"(d))
#define ADD2(d, v)    asm("add.rn.f32x2 %0, %1, %2;"     : "=l"(d) : "l"(d), "l"(v))
#define DUP2(d, f)    asm("mov.b64 %0, {%1, %1};"        : "=l"(d) : "f"(f))
#define UNPK2(lo, hi, v) asm("mov.b64 {%0, %1}, %2;" : "=f"(lo), "=f"(hi) : "l"(v))

// PDL: primary signals dependents may launch; secondary waits before touching
// dependent data. (sm_90 PTX, works under compute_103 virtual arch.)
#define PDL_TRIGGER() asm volatile("griddepcontrol.launch_dependents;" ::: "memory")
#define PDL_WAIT()    asm volatile("griddepcontrol.wait;" ::: "memory")

#define LDMX4(r0, r1, r2, r3, a) \
    asm volatile("ldmatrix.sync.aligned.m8n8.x4.shared.b16 {%0,%1,%2,%3}, [%4];" \
        : "=r"(r0), "=r"(r1), "=r"(r2), "=r"(r3) : "r"(a))
#define LDMX4T(r0, r1, r2, r3, a) \
    asm volatile("ldmatrix.sync.aligned.m8n8.x4.trans.shared.b16 {%0,%1,%2,%3}, [%4];" \
        : "=r"(r0), "=r"(r1), "=r"(r2), "=r"(r3) : "r"(a))
#define MMA16816(c, a, b0, b1) \
    asm volatile("mma.sync.aligned.m16n8k16.row.col.f32.f16.f16.f32 " \
        "{%0,%1,%2,%3}, {%4,%5,%6,%7}, {%8,%9}, {%0,%1,%2,%3};" \
        : "+f"((c)[0]), "+f"((c)[1]), "+f"((c)[2]), "+f"((c)[3]) \
        : "r"((a)[0]), "r"((a)[1]), "r"((a)[2]), "r"((a)[3]), "r"(b0), "r"(b1))

__device__ __forceinline__ uint32_t smem_u32(const void* p) {
    uint32_t a;
    asm("{ .reg .u64 t; cvta.to.shared.u64 t, %1; cvt.u32.u64 %0, t; }" : "=r"(a) : "l"(p));
    return a;
}

__device__ __forceinline__ int detect_is64(const void* e) {
    const int* p = (const int*)e;
    int allz = 1;
    #pragma unroll
    for (int k = 0; k < 16; k++)
        if (p[2 * k + 1] != 0) allz = 0;
    return allz;   // indices < 100000 -> if int64, every high word is 0
}

// ---------------- scratch (device globals; no allocation allowed) ----------
// g_count is SELF-CLEANING: zero at module load; k_scanC re-zeroes it after
// consuming, so every execution (incl. graph replays) sees zeros at entry.
__device__ int    g_count[NN];
__device__ int    g_rowptr[NN + 1];
__device__ int    g_rank[NE];              // per-edge rank within dst bucket
__device__ int    g_bsum[NB];
__device__ int    g_ssrc[NE];
__device__ float  g_dis[NN];
__device__ __half g_hs1h[(size_t)NN * FH];   // UNSCALED x@W1, fp16
__device__ __half g_a1h [(size_t)NN * FH];   // relu(agg1 + b1), fp16
__device__ __half g_hs2h[(size_t)NN * NC];   // dis-scaled a1@W2, fp16

// ------ histogram of dst + per-edge rank, 4 edges/thread -------------------
__global__ void k_hist(const void* __restrict__ e) {
    __shared__ int s64;
    if (threadIdx.x == 0) s64 = detect_is64(e);
    __syncthreads();
    int is64 = s64;
    int i = blockIdx.x * blockDim.x + threadIdx.x;
    if (i < NE / 4) {
        int d0, d1, d2, d3;
        if (is64) {
            longlong2 a = ((const longlong2*)e)[NE / 2 + 2 * i];
            longlong2 b = ((const longlong2*)e)[NE / 2 + 2 * i + 1];
            d0 = (int)a.x; d1 = (int)a.y; d2 = (int)b.x; d3 = (int)b.y;
        } else {
            int4 d = ((const int4*)e)[NE / 4 + i];
            d0 = d.x; d1 = d.y; d2 = d.z; d3 = d.w;
        }
        int r0 = atomicAdd(&g_count[d0], 1);
        int r1 = atomicAdd(&g_count[d1], 1);
        int r2 = atomicAdd(&g_count[d2], 1);
        int r3 = atomicAdd(&g_count[d3], 1);
        ((int4*)g_rank)[i] = make_int4(r0, r1, r2, r3);
    }
    PDL_TRIGGER();
}

// ---------------- scanA: per-1024-block exclusive scan ----------------------
__global__ void k_scanA() {
    __shared__ int sw[32];
    PDL_WAIT();   // g_count from k_hist
    int tid = threadIdx.x, lane = tid & 31, w = tid >> 5;
    int idx = blockIdx.x * 1024 + tid;
    int v = (idx < NN) ? g_count[idx] : 0;
    int x = v;
    #pragma unroll
    for (int d = 1; d < 32; d <<= 1) {
        int t = __shfl_up_sync(0xffffffffu, x, d);
        if (lane >= d) x += t;
    }
    if (lane == 31) sw[w] = x;
    __syncthreads();
    if (w == 0) {
        int y = sw[lane];
        #pragma unroll
        for (int d = 1; d < 32; d <<= 1) {
            int t = __shfl_up_sync(0xffffffffu, y, d);
            if (lane >= d) y += t;
        }
        sw[lane] = y;
    }
    __syncthreads();
    int wpre = (w > 0) ? sw[w - 1] : 0;
    if (idx < NN) g_rowptr[idx] = wpre + x - v;
    if (tid == 1023) g_bsum[blockIdx.x] = wpre + x;
    PDL_TRIGGER();
}

// ------ scanC: redundant scan of g_bsum + finalize rowptr/dis + CLEAN count -
__global__ void k_scanC() {
    __shared__ int boffS[NB];
    __shared__ int sw[4];
    PDL_WAIT();   // g_bsum / g_rowptr from k_scanA
    int tid = threadIdx.x, lane = tid & 31, w = tid >> 5;
    int v = 0, x = 0;
    if (tid < 128) {
        v = (tid < NB) ? g_bsum[tid] : 0;
        x = v;
        #pragma unroll
        for (int d = 1; d < 32; d <<= 1) {
            int t = __shfl_up_sync(0xffffffffu, x, d);
            if (lane >= d) x += t;
        }
        if (lane == 31) sw[w] = x;
    }
    __syncthreads();
    if (tid < NB) {
        int woff = 0;
        for (int i = 0; i < w; i++) woff += sw[i];
        boffS[tid] = woff + x - v;
    }
    __syncthreads();
    int i = blockIdx.x * blockDim.x + tid;
    if (i < NN) {
        int cnt = g_count[i];
        g_count[i] = 0;                        // self-clean for next run
        int rp = g_rowptr[i] + boffS[i >> 10];
        g_rowptr[i] = rp;
        g_dis[i]    = rsqrtf((float)(cnt + 1));  // +1 self loop
        if (i == 0) g_rowptr[NN] = NE;
    }
    PDL_TRIGGER();
}

// ------ counting-sort scatter — atomic-free, 4 edges/thread ----------------
__global__ void k_scatter(const void* __restrict__ e) {
    __shared__ int s64;
    if (threadIdx.x == 0) s64 = detect_is64(e);
    __syncthreads();
    int is64 = s64;
    int i = blockIdx.x * blockDim.x + threadIdx.x;
    if (i < NE / 4) {
        // independent loads first (edge list is a kernel input)
        int s0, s1, s2, s3, d0, d1, d2, d3;
        if (is64) {
            longlong2 sa = ((const longlong2*)e)[2 * i];
            longlong2 sb = ((const longlong2*)e)[2 * i + 1];
            longlong2 da = ((const longlong2*)e)[NE / 2 + 2 * i];
            longlong2 db = ((const longlong2*)e)[NE / 2 + 2 * i + 1];
            s0 = (int)sa.x; s1 = (int)sa.y; s2 = (int)sb.x; s3 = (int)sb.y;
            d0 = (int)da.x; d1 = (int)da.y; d2 = (int)db.x; d3 = (int)db.y;
        } else {
            int4 s = ((const int4*)e)[i];
            int4 d = ((const int4*)e)[NE / 4 + i];
            s0 = s.x; s1 = s.y; s2 = s.z; s3 = s.w;
            d0 = d.x; d1 = d.y; d2 = d.z; d3 = d.w;
        }
        PDL_WAIT();   // g_rank (hist) + g_rowptr (scanC)
        int4 rk = ((const int4*)g_rank)[i];
        g_ssrc[g_rowptr[d0] + rk.x] = s0;
        g_ssrc[g_rowptr[d1] + rk.y] = s1;
        g_ssrc[g_rowptr[d2] + rk.z] = s2;
        g_ssrc[g_rowptr[d3] + rk.w] = s3;
    } else {
        PDL_WAIT();
    }
}

// ------ GEMM1 (mma.sync fp16): hs1h = fp16(x @ W1), 128x128x128 per CTA ----
#define SP 136   // smem pitch in halves
__global__ void __launch_bounds__(256, 2) k_gemm1(const float* __restrict__ x,
                                                  const float* __restrict__ W) {
    extern __shared__ char smem[];
    __half* As = (__half*)smem;            // [128][SP] x tile
    __half* Ws = (__half*)(smem + 128 * SP * 2);  // [128][SP] W1 (k-major)
    uint32_t sbA = smem_u32(As), sbW = smem_u32(Ws);
    int tid = threadIdx.x, wid = tid >> 5, lane = tid & 31;
    int wr = wid & 3, wc = wid >> 2;
    int blockRow = blockIdx.x * 128;

    #pragma unroll
    for (int it = 0; it < 16; it++) {
        int t = tid + it * 256;
        int r = t >> 5, c4 = (t & 31) * 4;
        int grow = blockRow + r;
        float4 v = make_float4(0.f, 0.f, 0.f, 0.f);
        if (grow < NN) v = *(const float4*)&x[(size_t)grow * FIN + c4];
        __half2 h0 = __floats2half2_rn(v.x, v.y);
        __half2 h1 = __floats2half2_rn(v.z, v.w);
        *(uint2*)&As[r * SP + c4] = make_uint2(*(uint32_t*)&h0, *(uint32_t*)&h1);
    }
    #pragma unroll
    for (int it = 0; it < 16; it++) {
        int t = tid + it * 256;
        int k = t >> 5, n4 = (t & 31) * 4;
        float4 v = *(const float4*)&W[(size_t)k * FH + n4];
        __half2 h0 = __floats2half2_rn(v.x, v.y);
        __half2 h1 = __floats2half2_rn(v.z, v.w);
        *(uint2*)&Ws[k * SP + n4] = make_uint2(*(uint32_t*)&h0, *(uint32_t*)&h1);
    }
    __syncthreads();

    float c[2][8][4];
    #pragma unroll
    for (int mt = 0; mt < 2; mt++)
        #pragma unroll
        for (int nt = 0; nt < 8; nt++)
            #pragma unroll
            for (int i = 0; i < 4; i++) c[mt][nt][i] = 0.f;

    int lr = lane & 15, lh = lane >> 4;
    #pragma unroll
    for (int ks = 0; ks < 8; ks++) {
        uint32_t a[2][4];
        #pragma unroll
        for (int mt = 0; mt < 2; mt++) {
            uint32_t ad = sbA + ((wr * 32 + mt * 16 + lr) * SP + ks * 16 + 8 * lh) * 2;
            LDMX4(a[mt][0], a[mt][1], a[mt][2], a[mt][3], ad);
        }
        uint32_t b[4][4];
        #pragma unroll
        for (int np = 0; np < 4; np++) {
            uint32_t bd = sbW + ((ks * 16 + lr) * SP + wc * 64 + np * 16 + 8 * lh) * 2;
            LDMX4T(b[np][0], b[np][1], b[np][2], b[np][3], bd);
        }
        #pragma unroll
        for (int mt = 0; mt < 2; mt++)
            #pragma unroll
            for (int nt = 0; nt < 8; nt++)
                MMA16816(c[mt][nt], a[mt], b[nt >> 1][(nt & 1) * 2], b[nt >> 1][(nt & 1) * 2 + 1]);
    }
    __syncthreads();
    __half* stage = As;
    int g = lane >> 2, tc = (lane & 3) * 2;
    #pragma unroll
    for (int mt = 0; mt < 2; mt++)
        #pragma unroll
        for (int nt = 0; nt < 8; nt++) {
            int row = wr * 32 + mt * 16 + g;
            int col = wc * 64 + nt * 8 + tc;
            __half2 lo = __floats2half2_rn(c[mt][nt][0], c[mt][nt][1]);
            __half2 hi = __floats2half2_rn(c[mt][nt][2], c[mt][nt][3]);
            *(__half2*)&stage[row * SP + col] = lo;
            *(__half2*)&stage[(row + 8) * SP + col] = hi;
        }
    __syncthreads();
    #pragma unroll
    for (int it = 0; it < 8; it++) {
        int t = tid + it * 256;
        int r = t >> 4, c8 = (t & 15) * 8;
        int grow = blockRow + r;
        if (grow < NN)
            *(uint4*)&g_hs1h[(size_t)grow * FH + c8] = *(const uint4*)&stage[r * SP + c8];
    }
    PDL_TRIGGER();
}

// ------ Agg layer 1: warp per node, half-warp per edge (R8 version) --------
__global__ void k_agg1(const float* __restrict__ b1) {
    PDL_WAIT();   // hs1h (gemm1, same-stream PDL edge); CSR via event edge
    int warp = threadIdx.x >> 5, lane = threadIdx.x & 31;
    int node = blockIdx.x * 8 + warp;
    if (node >= NN) { PDL_TRIGGER(); return; }   // warp-uniform
    int h = lane >> 4, q = lane & 15;
    const uint4* hv = (const uint4*)g_hs1h;
    float dnode = g_dis[node];
    u64 a0 = 0ULL, a1 = 0ULL, a2 = 0ULL, a3 = 0ULL;
    {   // self-loop only on half 0
        float ds = (h == 0) ? dnode : 0.f;
        u64 dd;
        DUP2(dd, ds);
        uint4 r = hv[(size_t)node * 16 + q];
        float2 f0 = __half22float2(*(__half2*)&r.x);
        float2 f1 = __half22float2(*(__half2*)&r.y);
        float2 f2 = __half22float2(*(__half2*)&r.z);
        float2 f3 = __half22float2(*(__half2*)&r.w);
        FMA2(a0, *(u64*)&f0, dd); FMA2(a1, *(u64*)&f1, dd);
        FMA2(a2, *(u64*)&f2, dd); FMA2(a3, *(u64*)&f3, dd);
    }
    int s0 = g_rowptr[node], s1 = g_rowptr[node + 1];
    for (int j = s0 + h; j < s1; j += 2) {
        int ss = __ldcs(&g_ssrc[j]);          // 16-lane broadcast
        float d = g_dis[ss];
        u64 dd;
        DUP2(dd, d);
        uint4 r = hv[(size_t)ss * 16 + q];
        float2 f0 = __half22float2(*(__half2*)&r.x);
        float2 f1 = __half22float2(*(__half2*)&r.y);
        float2 f2 = __half22float2(*(__half2*)&r.z);
        float2 f3 = __half22float2(*(__half2*)&r.w);
        FMA2(a0, *(u64*)&f0, dd); FMA2(a1, *(u64*)&f1, dd);
        FMA2(a2, *(u64*)&f2, dd); FMA2(a3, *(u64*)&f3, dd);
    }
    u64 o0 = __shfl_xor_sync(0xffffffffu, a0, 16);
    u64 o1 = __shfl_xor_sync(0xffffffffu, a1, 16);
    u64 o2 = __shfl_xor_sync(0xffffffffu, a2, 16);
    u64 o3 = __shfl_xor_sync(0xffffffffu, a3, 16);
    ADD2(a0, o0); ADD2(a1, o1); ADD2(a2, o2); ADD2(a3, o3);
    if (h == 0) {
        float f[8];
        UNPK2(f[0], f[1], a0); UNPK2(f[2], f[3], a1);
        UNPK2(f[4], f[5], a2); UNPK2(f[6], f[7], a3);
        float4 bA = ((const float4*)b1)[q * 2];
        float4 bB = ((const float4*)b1)[q * 2 + 1];
        float o[8];
        o[0] = fmaxf(fmaf(f[0], dnode, bA.x), 0.f);
        o[1] = fmaxf(fmaf(f[1], dnode, bA.y), 0.f);
        o[2] = fmaxf(fmaf(f[2], dnode, bA.z), 0.f);
        o[3] = fmaxf(fmaf(f[3], dnode, bA.w), 0.f);
        o[4] = fmaxf(fmaf(f[4], dnode, bB.x), 0.f);
        o[5] = fmaxf(fmaf(f[5], dnode, bB.y), 0.f);
        o[6] = fmaxf(fmaf(f[6], dnode, bB.z), 0.f);
        o[7] = fmaxf(fmaf(f[7], dnode, bB.w), 0.f);
        __half2 h0 = __floats2half2_rn(o[0], o[1]);
        __half2 h1 = __floats2half2_rn(o[2], o[3]);
        __half2 h2 = __floats2half2_rn(o[4], o[5]);
        __half2 h3 = __floats2half2_rn(o[6], o[7]);
        uint4 st = make_uint4(*(uint32_t*)&h0, *(uint32_t*)&h1,
                              *(uint32_t*)&h2, *(uint32_t*)&h3);
        ((uint4*)g_a1h)[(size_t)node * 16 + q] = st;
    }
    PDL_TRIGGER();
}

// ------- GEMM2 (f32x2): hs2h[r] = fp16(dis[r] * (a1[r] @ W2)) ---------------
__global__ void k_gemm2(const float* __restrict__ W2) {
    __shared__ float as[64][132];
    __shared__ float ws2[FH * NC];
    int tid = threadIdx.x;
    int n  = tid >> 2;
    int cg = (tid & 3) * 4;
    int blockRow = blockIdx.x * 64;

    // W2 is a kernel input — stage it BEFORE the dependency wait
    #pragma unroll
    for (int i = 0; i < 8; i++) {
        int t = tid + i * 256;
        ws2[t] = W2[t];
    }
    PDL_WAIT();   // a1h / dis from agg1
    #pragma unroll
    for (int it = 0; it < 4; it++) {
        int t = tid + it * 256;
        int row = t >> 4, c8 = (t & 15) * 8;
        int grow = blockRow + row;
        uint4 r = make_uint4(0u, 0u, 0u, 0u);
        if (grow < NN) r = ((const uint4*)g_a1h)[(size_t)grow * 16 + (t & 15)];
        float2 f0 = __half22float2(*(__half2*)&r.x);
        float2 f1 = __half22float2(*(__half2*)&r.y);
        float2 f2 = __half22float2(*(__half2*)&r.z);
        float2 f3 = __half22float2(*(__half2*)&r.w);
        as[row][c8 + 0] = f0.x; as[row][c8 + 1] = f0.y;
        as[row][c8 + 2] = f1.x; as[row][c8 + 3] = f1.y;
        as[row][c8 + 4] = f2.x; as[row][c8 + 5] = f2.y;
        as[row][c8 + 6] = f3.x; as[row][c8 + 7] = f3.y;
    }
    __syncthreads();

    u64 acc2[2] = {0ULL, 0ULL};
    #pragma unroll 8
    for (int k = 0; k < FH; k++) {
        float av = as[n][k];
        u64 a2;
        DUP2(a2, av);
        ulonglong2 wv = *(const ulonglong2*)&ws2[k * NC + cg];
        FMA2(acc2[0], a2, wv.x);
        FMA2(acc2[1], a2, wv.y);
    }
    int row = blockRow + n;
    if (row < NN) {
        float l0, h0, l1, h1;
        UNPK2(l0, h0, acc2[0]); UNPK2(l1, h1, acc2[1]);
        float dv = g_dis[row];
        __half2 p0 = __floats2half2_rn(l0 * dv, h0 * dv);
        __half2 p1 = __floats2half2_rn(l1 * dv, h1 * dv);
        *(uint2*)&g_hs2h[(size_t)row * NC + cg] = make_uint2(*(uint32_t*)&p0, *(uint32_t*)&p1);
    }
    PDL_TRIGGER();
}

// ------- Agg layer 2 + bias + log_softmax (2 lanes/node — R8 version) ------
__global__ void k_agg2(const float* __restrict__ b2, float* __restrict__ out) {
    PDL_WAIT();   // hs2h from gemm2
    int gt = blockIdx.x * blockDim.x + threadIdx.x;
    int node = gt >> 1;
    int q = gt & 1;
    int node_c = (node < NN) ? node : (NN - 1);
    const uint4* hv = (const uint4*)g_hs2h;   // 2 uint4 per row
    u64 aA0, aA1, aA2, aA3;
    {
        uint4 r = hv[(size_t)node_c * 2 + q];
        float2 f0 = __half22float2(*(__half2*)&r.x);
        float2 f1 = __half22float2(*(__half2*)&r.y);
        float2 f2 = __half22float2(*(__half2*)&r.z);
        float2 f3 = __half22float2(*(__half2*)&r.w);
        aA0 = *(u64*)&f0; aA1 = *(u64*)&f1; aA2 = *(u64*)&f2; aA3 = *(u64*)&f3;
    }
    int s0 = g_rowptr[node_c], s1 = g_rowptr[node_c + 1];
    for (int j = s0; j < s1; j++) {
        int s = __ldcs(&g_ssrc[j]);
        uint4 r = hv[(size_t)s * 2 + q];
        float2 f0 = __half22float2(*(__half2*)&r.x);
        float2 f1 = __half22float2(*(__half2*)&r.y);
        float2 f2 = __half22float2(*(__half2*)&r.z);
        float2 f3 = __half22float2(*(__half2*)&r.w);
        ADD2(aA0, *(u64*)&f0); ADD2(aA1, *(u64*)&f1);
        ADD2(aA2, *(u64*)&f2); ADD2(aA3, *(u64*)&f3);
    }
    float f[8];
    UNPK2(f[0], f[1], aA0); UNPK2(f[2], f[3], aA1);
    UNPK2(f[4], f[5], aA2); UNPK2(f[6], f[7], aA3);
    float dv = g_dis[node_c];
    float4 bA = ((const float4*)b2)[q * 2];
    float4 bB = ((const float4*)b2)[q * 2 + 1];
    float v[8];
    v[0] = fmaf(f[0], dv, bA.x); v[1] = fmaf(f[1], dv, bA.y);
    v[2] = fmaf(f[2], dv, bA.z); v[3] = fmaf(f[3], dv, bA.w);
    v[4] = fmaf(f[4], dv, bB.x); v[5] = fmaf(f[5], dv, bB.y);
    v[6] = fmaf(f[6], dv, bB.z); v[7] = fmaf(f[7], dv, bB.w);
    float m = v[0];
    #pragma unroll
    for (int i = 1; i < 8; i++) m = fmaxf(m, v[i]);
    m = fmaxf(m, __shfl_xor_sync(0xffffffffu, m, 1));
    float e = 0.f;
    #pragma unroll
    for (int i = 0; i < 8; i++) e += expf(v[i] - m);
    e += __shfl_xor_sync(0xffffffffu, e, 1);
    float lse = m + logf(e);
    if (node < NN) {
        float4 o0 = make_float4(v[0] - lse, v[1] - lse, v[2] - lse, v[3] - lse);
        float4 o1 = make_float4(v[4] - lse, v[5] - lse, v[6] - lse, v[7] - lse);
        ((float4*)out)[(size_t)node * 4 + q * 2]     = o0;
        ((float4*)out)[(size_t)node * 4 + q * 2 + 1] = o1;
    }
}

// ---------------- launch: fork CSR || gemm1, PDL on dependent edges --------
template <typename F, typename... A>
static inline void launch_pdl(F f, dim3 grid, dim3 block, size_t smem,
                              cudaStream_t st, A... args) {
    cudaLaunchConfig_t cfg = {};
    cfg.gridDim = grid;
    cfg.blockDim = block;
    cfg.dynamicSmemBytes = smem;
    cfg.stream = st;
    cudaLaunchAttribute at[1];
    at[0].id = cudaLaunchAttributeProgrammaticStreamSerialization;
    at[0].val.programmaticStreamSerializationAllowed = 1;
    cfg.attrs = at;
    cfg.numAttrs = 1;
    cudaLaunchKernelEx(&cfg, f, args...);
}

extern "C" void kernel_launch(void* const* d_in, const int* in_sizes, int n_in,
                              void* d_out, int out_size) {
    const float* x  = (const float*)d_in[0];
    const void*  ei = d_in[1];
    const float* W1 = (const float*)d_in[2];
    const float* b1 = (const float*)d_in[3];
    const float* W2 = (const float*)d_in[4];
    const float* b2 = (const float*)d_in[5];
    float* out = (float*)d_out;

    const int GEMM1_SMEM = 2 * 128 * SP * 2;   // 69632
    cudaFuncSetAttribute(k_gemm1, cudaFuncAttributeMaxDynamicSharedMemorySize, GEMM1_SMEM);

    cudaStream_t s1;
    cudaStreamCreate(&s1);
    cudaEvent_t eFork, eJoin;
    cudaEventCreateWithFlags(&eFork, cudaEventDisableTiming);
    cudaEventCreateWithFlags(&eJoin, cudaEventDisableTiming);

    cudaEventRecord(eFork, 0);
    cudaStreamWaitEvent(s1, eFork, 0);
    k_hist<<<(NE / 4 + 255) / 256, 256, 0, s1>>>(ei);                    // 1
    launch_pdl(k_scanA, NB, 1024, 0, s1);                                // 2
    launch_pdl(k_scanC, (NN + 255) / 256, 256, 0, s1);                   // 3
    launch_pdl(k_scatter, (NE / 4 + 255) / 256, 256, 0, s1, ei);         // 4 -> profiled
    cudaEventRecord(eJoin, s1);

    k_gemm1<<<(NN + 127) / 128, 256, GEMM1_SMEM>>>(x, W1);               // parallel w/ CSR

    cudaStreamWaitEvent(0, eJoin, 0);
    launch_pdl(k_agg1, (NN + 7) / 8, 256, 0, (cudaStream_t)0, b1);       // PDL vs gemm1
    launch_pdl(k_gemm2, (NN + 63) / 64, 256, 0, (cudaStream_t)0, W2);
    launch_pdl(k_agg2, (NN * 2 + 255) / 256, 256, 0, (cudaStream_t)0, b2, out);
    // streams/events intentionally not destroyed (host-side objects only)
}